// round 2
// baseline (speedup 1.0000x reference)
#include <cuda_runtime.h>
#include <cstdint>

// Problem constants
#define BB   16
#define FIN  3
#define NV   170
#define TT   288
#define HH   64
#define OO   64
#define KK   3
#define KSZ  3

// Fused-kernel tiling
#define NP    192          // padded vertex rows (16 ty * 12 rows)
#define RPT   12           // rows per thread
#define CH    34           // m-chunk size (5 chunks of 34 = 170)
#define NCHUNK 5

// Shared memory layout (floats)
#define Z_OFF      0
#define Z_SIZE     (KK * NP * HH)            // 36864
#define TS_OFF     (Z_OFF + Z_SIZE)          // 36864
#define TS_SIZE    (NV * HH)                 // 10880
#define CHS_OFF    (TS_OFF + TS_SIZE)        // 47744
#define CHS_SIZE   (CH * NP)                 // 6528
#define XS_OFF     (CHS_OFF + CHS_SIZE)      // 54272  xs[f][m][4]
#define XS_SIZE    (FIN * NV * 4)            // 2040
#define CW_OFF     (XS_OFF + XS_SIZE)        // 56312  conv w [64][9]
#define CW_SIZE    (HH * 9)                  // 576
#define CB_OFF     (CW_OFF + CW_SIZE)        // 56888
#define CB_SIZE    (HH)                      // 64
// theta / residual overlay on t_s + cheb_s region (17408 floats available)
#define TH_OFF     (TS_OFF)                  // 36864
#define TH_SIZE    (KK * HH * OO)            // 12288
#define RW_OFF     (TH_OFF + TH_SIZE)        // 49152
#define RB_OFF     (RW_OFF + OO * FIN)       // 49344
#define SMEM_FLOATS (CB_OFF + CB_SIZE)       // 56952
#define SMEM_BYTES  (SMEM_FLOATS * 4)        // 227808

// Small scratch only (no giant globals)
__device__ float g_chebT[KK * NV * NV];      // [K,m,n]  ~347 KB

// ---------------------------------------------------------------------------
// Kernel 1: cheb transpose  cheb[k][n][m] -> g_chebT[k][m][n]
// ---------------------------------------------------------------------------
__global__ void cheb_transpose_kernel(const float* __restrict__ cheb) {
    int k = blockIdx.x;
    for (int i = threadIdx.x; i < NV * NV; i += blockDim.x) {
        int n = i / NV, m = i % NV;
        g_chebT[(k * NV + m) * NV + n] = cheb[(k * NV + n) * NV + m];
    }
}

// ---------------------------------------------------------------------------
// Kernel 2: fully fused: temporal conv + ChebConv + theta + ReLU + residual.
// One block per (b,tau). 256 threads.
// ---------------------------------------------------------------------------
__global__ __launch_bounds__(256, 1) void fused_kernel(
    const float* __restrict__ x, const float* __restrict__ conv_w,
    const float* __restrict__ conv_b, const float* __restrict__ theta,
    const float* __restrict__ res_w, const float* __restrict__ res_b,
    float* __restrict__ out)
{
    extern __shared__ float smem[];
    float* z_s    = smem + Z_OFF;
    float* t_s    = smem + TS_OFF;
    float* cheb_s = smem + CHS_OFF;
    float* xs     = smem + XS_OFF;     // [FIN][NV][4] (slot 0..2 = tau-1..tau+1)
    float* cw_s   = smem + CW_OFF;
    float* cb_s   = smem + CB_OFF;
    float* th_s   = smem + TH_OFF;
    float* rw_s   = smem + RW_OFF;
    float* rb_s   = smem + RB_OFF;

    const int tid = threadIdx.x;
    const int tx = tid & 15, ty = tid >> 4;
    const int tau = blockIdx.x, b = blockIdx.y;

    // ---- load x window [FIN][NV][tau-1..tau+1] and conv weights ----
    for (int i = tid; i < FIN * NV; i += 256) {
        int f = i / NV, m = i % NV;
        const float* xr = x + (((size_t)b * FIN + f) * NV + m) * TT + tau;
        float* d = &xs[(f * NV + m) * 4];
        d[0] = (tau > 0)      ? xr[-1] : 0.f;
        d[1] = xr[0];
        d[2] = (tau < TT - 1) ? xr[1]  : 0.f;
    }
    for (int i = tid; i < CW_SIZE; i += 256) cw_s[i] = conv_w[i];
    if (tid < HH) cb_s[tid] = conv_b[tid];
    __syncthreads();

    // ---- temporal conv + ReLU -> t_s[m][c] ----
    {
        int c = tid & 63, tl = tid >> 6;
        float wr[9];
#pragma unroll
        for (int i = 0; i < 9; i++) wr[i] = cw_s[c * 9 + i];
        float bv = cb_s[c];
        for (int m = tl; m < NV; m += 4) {
            float acc = bv;
#pragma unroll
            for (int f = 0; f < FIN; f++) {
                const float* xm = &xs[(f * NV + m) * 4];
                acc += xm[0] * wr[f * 3 + 0];
                acc += xm[1] * wr[f * 3 + 1];
                acc += xm[2] * wr[f * 3 + 2];
            }
            t_s[m * HH + c] = fmaxf(acc, 0.f);
        }
    }
    __syncthreads();

    float acc[RPT][4];

    // ---- stage B: z[k][n][c] = sum_m chebT[k][m][n] * t[m][c] ----
    for (int k = 0; k < KK; k++) {
#pragma unroll
        for (int r = 0; r < RPT; r++)
#pragma unroll
            for (int j = 0; j < 4; j++) acc[r][j] = 0.f;

        for (int ch = 0; ch < NCHUNK; ch++) {
            __syncthreads();
            const float* cb = g_chebT + (k * NV + ch * CH) * NV;
            for (int i = tid; i < CH * NP; i += 256) {
                int mm = i / NP, nn = i % NP;
                cheb_s[i] = (nn < NV) ? cb[mm * NV + nn] : 0.f;
            }
            __syncthreads();

#pragma unroll 2
            for (int mm = 0; mm < CH; mm++) {
                int m = ch * CH + mm;
                float4 tv = *(const float4*)&t_s[m * HH + 4 * tx];
                float cc[RPT];
                const float* crow = &cheb_s[mm * NP + ty * RPT];
                *(float4*)&cc[0] = *(const float4*)&crow[0];
                *(float4*)&cc[4] = *(const float4*)&crow[4];
                *(float4*)&cc[8] = *(const float4*)&crow[8];
#pragma unroll
                for (int r = 0; r < RPT; r++) {
                    acc[r][0] += cc[r] * tv.x;
                    acc[r][1] += cc[r] * tv.y;
                    acc[r][2] += cc[r] * tv.z;
                    acc[r][3] += cc[r] * tv.w;
                }
            }
        }
#pragma unroll
        for (int r = 0; r < RPT; r++) {
            int n = ty * RPT + r;
            *(float4*)&z_s[(k * NP + n) * HH + 4 * tx] =
                make_float4(acc[r][0], acc[r][1], acc[r][2], acc[r][3]);
        }
    }

    // ---- overlay theta / residual weights onto t_s+cheb_s region ----
    __syncthreads();
    for (int i = tid; i < TH_SIZE; i += 256) th_s[i] = theta[i];
    for (int i = tid; i < OO * FIN; i += 256) rw_s[i] = res_w[i];
    if (tid < OO) rb_s[tid] = res_b[tid];
    __syncthreads();

    // ---- stage C: gcn[n][o] = sum_k sum_c z[k][n][c] * theta[k][c][o] ----
    float g[RPT][4];
#pragma unroll
    for (int r = 0; r < RPT; r++)
#pragma unroll
        for (int j = 0; j < 4; j++) g[r][j] = 0.f;

    for (int k = 0; k < KK; k++) {
#pragma unroll 2
        for (int c4 = 0; c4 < HH / 4; c4++) {
            int c = c4 * 4;
            float4 th0 = *(const float4*)&th_s[((k * HH + c + 0) * OO) + 4 * tx];
            float4 th1 = *(const float4*)&th_s[((k * HH + c + 1) * OO) + 4 * tx];
            float4 th2 = *(const float4*)&th_s[((k * HH + c + 2) * OO) + 4 * tx];
            float4 th3 = *(const float4*)&th_s[((k * HH + c + 3) * OO) + 4 * tx];
#pragma unroll
            for (int r = 0; r < RPT; r++) {
                float4 zv = *(const float4*)&z_s[(k * NP + ty * RPT + r) * HH + c];
                g[r][0] += zv.x * th0.x; g[r][0] += zv.y * th1.x;
                g[r][0] += zv.z * th2.x; g[r][0] += zv.w * th3.x;
                g[r][1] += zv.x * th0.y; g[r][1] += zv.y * th1.y;
                g[r][1] += zv.z * th2.y; g[r][1] += zv.w * th3.y;
                g[r][2] += zv.x * th0.z; g[r][2] += zv.y * th1.z;
                g[r][2] += zv.z * th2.z; g[r][2] += zv.w * th3.z;
                g[r][3] += zv.x * th0.w; g[r][3] += zv.y * th1.w;
                g[r][3] += zv.z * th2.w; g[r][3] += zv.w * th3.w;
            }
        }
    }

    // ---- epilogue: relu(gcn) + residual, scatter to out[b][o][n][tau] ----
    // residual uses xs[f][n][1] == x[b,f,n,tau] still live in smem
#pragma unroll
    for (int r = 0; r < RPT; r++) {
        int n = ty * RPT + r;
        if (n < NV) {
            float x0 = xs[(0 * NV + n) * 4 + 1];
            float x1 = xs[(1 * NV + n) * 4 + 1];
            float x2 = xs[(2 * NV + n) * 4 + 1];
#pragma unroll
            for (int j = 0; j < 4; j++) {
                int o = 4 * tx + j;
                float v = fmaxf(g[r][j], 0.f)
                        + x0 * rw_s[o * 3 + 0] + x1 * rw_s[o * 3 + 1]
                        + x2 * rw_s[o * 3 + 2] + rb_s[o];
                out[(((size_t)b * OO + o) * NV + n) * TT + tau] = v;
            }
        }
    }
}

// ---------------------------------------------------------------------------
extern "C" void kernel_launch(void* const* d_in, const int* in_sizes, int n_in,
                              void* d_out, int out_size)
{
    const float* x      = (const float*)d_in[0];
    // d_in[1] = adj (unused by forward)
    const float* cheb   = (const float*)d_in[2];
    const float* conv_w = (const float*)d_in[3];
    const float* conv_b = (const float*)d_in[4];
    const float* theta  = (const float*)d_in[5];
    const float* res_w  = (const float*)d_in[6];
    const float* res_b  = (const float*)d_in[7];
    float* out = (float*)d_out;

    cudaFuncSetAttribute(fused_kernel,
                         cudaFuncAttributeMaxDynamicSharedMemorySize, SMEM_BYTES);

    cheb_transpose_kernel<<<KK, 256>>>(cheb);
    fused_kernel<<<dim3(TT, BB), 256, SMEM_BYTES>>>(
        x, conv_w, conv_b, theta, res_w, res_b, out);
}

// round 4
// speedup vs baseline: 1.1659x; 1.1659x over previous
#include <cuda_runtime.h>
#include <cstdint>

// Problem constants
#define BB   16
#define FIN  3
#define NV   170
#define TT   288
#define HH   64
#define OO   64
#define KK   3
#define KSZ  3

// Fused-kernel tiling: 512 threads, tx = tid&15 (4 cols), ty = tid>>4 (6 rows)
#define NTHR  512
#define NP    192          // padded vertex rows (32 ty * 6 rows)
#define RPT   6            // rows per thread
#define RPP   3            // row pairs per thread
#define CH    34           // m-chunk size (5 chunks of 34 = 170)
#define NCHUNK 5

// Shared memory layout (floats)
#define Z_OFF      0
#define Z_SIZE     (KK * NP * HH)            // 36864
#define TS_OFF     (Z_OFF + Z_SIZE)          // 36864
#define TS_SIZE    (NV * HH)                 // 10880
#define CHS_OFF    (TS_OFF + TS_SIZE)        // 47744
#define CHS_SIZE   (CH * NP)                 // 6528
#define XS_OFF     (CHS_OFF + CHS_SIZE)      // 54272  xs[f][m][4]
#define XS_SIZE    (FIN * NV * 4)            // 2040
#define CW_OFF     (XS_OFF + XS_SIZE)        // 56312
#define CW_SIZE    (HH * 9)                  // 576
#define CB_OFF     (CW_OFF + CW_SIZE)        // 56888
#define CB_SIZE    (HH)                      // 64
// theta (c-interleaved pairs) / residual overlay on t_s+cheb_s region
#define TH_OFF     (TS_OFF)                  // 36864
#define TH_SIZE    (KK * (HH/2) * OO * 2)    // 12288
#define RW_OFF     (TH_OFF + TH_SIZE)        // 49152
#define RB_OFF     (RW_OFF + OO * FIN)       // 49344
#define SMEM_FLOATS (CB_OFF + CB_SIZE)       // 56952
#define SMEM_BYTES  (SMEM_FLOATS * 4)        // 227808

__device__ float g_chebT[KK * NV * NV];      // [K,m,n]  ~347 KB

// packed f32x2 helpers
__device__ __forceinline__ void fma2(unsigned long long& d,
                                     unsigned long long a,
                                     unsigned long long b) {
    asm("fma.rn.f32x2 %0, %1, %2, %0;" : "+l"(d) : "l"(a), "l"(b));
}
__device__ __forceinline__ unsigned long long pack2(float lo, float hi) {
    unsigned long long r;
    asm("mov.b64 %0, {%1, %2};" : "=l"(r) : "f"(lo), "f"(hi));
    return r;
}
__device__ __forceinline__ void unpack2(float& lo, float& hi,
                                        unsigned long long v) {
    asm("mov.b64 {%0, %1}, %2;" : "=f"(lo), "=f"(hi) : "l"(v));
}

// ---------------------------------------------------------------------------
// Kernel 1: cheb transpose  cheb[k][n][m] -> g_chebT[k][m][n]
// ---------------------------------------------------------------------------
__global__ void cheb_transpose_kernel(const float* __restrict__ cheb) {
    int k = blockIdx.x;
    for (int i = threadIdx.x; i < NV * NV; i += blockDim.x) {
        int n = i / NV, m = i % NV;
        g_chebT[(k * NV + m) * NV + n] = cheb[(k * NV + n) * NV + m];
    }
}

// ---------------------------------------------------------------------------
// Kernel 2: fully fused, one block per (b,tau), 512 threads.
// ---------------------------------------------------------------------------
__global__ __launch_bounds__(NTHR, 1) void fused_kernel(
    const float* __restrict__ x, const float* __restrict__ conv_w,
    const float* __restrict__ conv_b, const float* __restrict__ theta,
    const float* __restrict__ res_w, const float* __restrict__ res_b,
    float* __restrict__ out)
{
    extern __shared__ float smem[];
    float* z_s    = smem + Z_OFF;
    float* t_s    = smem + TS_OFF;
    float* cheb_s = smem + CHS_OFF;
    float* xs     = smem + XS_OFF;
    float* cw_s   = smem + CW_OFF;
    float* cb_s   = smem + CB_OFF;
    float* th_s   = smem + TH_OFF;
    float* rw_s   = smem + RW_OFF;
    float* rb_s   = smem + RB_OFF;

    const int tid = threadIdx.x;
    const int tx = tid & 15, ty = tid >> 4;
    const int tau = blockIdx.x, b = blockIdx.y;
    const int row0 = ty * RPT;

    // ---- load x window [FIN][NV][tau-1..tau+1] and conv weights ----
    for (int i = tid; i < FIN * NV; i += NTHR) {
        int f = i / NV, m = i % NV;
        const float* xr = x + (((size_t)b * FIN + f) * NV + m) * TT + tau;
        float* d = &xs[(f * NV + m) * 4];
        d[0] = (tau > 0)      ? xr[-1] : 0.f;
        d[1] = xr[0];
        d[2] = (tau < TT - 1) ? xr[1]  : 0.f;
    }
    for (int i = tid; i < CW_SIZE; i += NTHR) cw_s[i] = conv_w[i];
    if (tid < HH) cb_s[tid] = conv_b[tid];
    __syncthreads();

    // ---- temporal conv + ReLU -> t_s[m][c] ----
    {
        int c = tid & 63, tl = tid >> 6;   // 8 m-lanes
        float wr[9];
#pragma unroll
        for (int i = 0; i < 9; i++) wr[i] = cw_s[c * 9 + i];
        float bv = cb_s[c];
        for (int m = tl; m < NV; m += 8) {
            float acc = bv;
#pragma unroll
            for (int f = 0; f < FIN; f++) {
                const float* xm = &xs[(f * NV + m) * 4];
                acc += xm[0] * wr[f * 3 + 0];
                acc += xm[1] * wr[f * 3 + 1];
                acc += xm[2] * wr[f * 3 + 2];
            }
            t_s[m * HH + c] = fmaxf(acc, 0.f);
        }
    }
    __syncthreads();

    // ---- stage B: z[k][n][c] = sum_m chebT[k][m][n] * t[m][c] ----
    // acc2[rp][j]: packed over row pair (row0+2rp, row0+2rp+1), col 4tx+j
    unsigned long long acc2[RPP][4];
    for (int k = 0; k < KK; k++) {
#pragma unroll
        for (int rp = 0; rp < RPP; rp++)
#pragma unroll
            for (int j = 0; j < 4; j++) acc2[rp][j] = 0ULL;

        for (int ch = 0; ch < NCHUNK; ch++) {
            __syncthreads();
            const float* cb = g_chebT + (k * NV + ch * CH) * NV;
            for (int i = tid; i < CH * NP; i += NTHR) {
                int mm = i / NP, nn = i % NP;
                cheb_s[i] = (nn < NV) ? cb[mm * NV + nn] : 0.f;
            }
            __syncthreads();

#pragma unroll 2
            for (int mm = 0; mm < CH; mm++) {
                int m = ch * CH + mm;
                float4 tv = *(const float4*)&t_s[m * HH + 4 * tx];
                unsigned long long tvx = pack2(tv.x, tv.x);
                unsigned long long tvy = pack2(tv.y, tv.y);
                unsigned long long tvz = pack2(tv.z, tv.z);
                unsigned long long tvw = pack2(tv.w, tv.w);
                const unsigned long long* crow =
                    (const unsigned long long*)&cheb_s[mm * NP + row0];
#pragma unroll
                for (int rp = 0; rp < RPP; rp++) {
                    unsigned long long cc = crow[rp];
                    fma2(acc2[rp][0], cc, tvx);
                    fma2(acc2[rp][1], cc, tvy);
                    fma2(acc2[rp][2], cc, tvz);
                    fma2(acc2[rp][3], cc, tvw);
                }
            }
        }
#pragma unroll
        for (int rp = 0; rp < RPP; rp++) {
            float lo[4], hi[4];
#pragma unroll
            for (int j = 0; j < 4; j++) unpack2(lo[j], hi[j], acc2[rp][j]);
            int n = row0 + 2 * rp;
            *(float4*)&z_s[(k * NP + n)     * HH + 4 * tx] =
                make_float4(lo[0], lo[1], lo[2], lo[3]);
            *(float4*)&z_s[(k * NP + n + 1) * HH + 4 * tx] =
                make_float4(hi[0], hi[1], hi[2], hi[3]);
        }
    }

    // ---- overlay theta (c-interleaved pairs) / residual weights ----
    __syncthreads();
    for (int i = tid; i < KK * HH * OO; i += NTHR) {
        int k = i / (HH * OO), c = (i / OO) % HH, o = i % OO;
        th_s[((k * (HH / 2) + (c >> 1)) * OO + o) * 2 + (c & 1)] = theta[i];
    }
    for (int i = tid; i < OO * FIN; i += NTHR) rw_s[i] = res_w[i];
    if (tid < OO) rb_s[tid] = res_b[tid];
    __syncthreads();

    // ---- stage C: gcn[n][o] = sum_k sum_c z[k][n][c] * theta[k][c][o] ----
    // accC[r][j]: packed over c-pair lanes, reduced at the end
    unsigned long long accC[RPT][4];
#pragma unroll
    for (int r = 0; r < RPT; r++)
#pragma unroll
        for (int j = 0; j < 4; j++) accC[r][j] = 0ULL;

    for (int k = 0; k < KK; k++) {
#pragma unroll 2
        for (int c4 = 0; c4 < HH / 4; c4++) {
            int c2a = 2 * c4, c2b = 2 * c4 + 1;
            unsigned long long th0[4], th1[4];
#pragma unroll
            for (int j = 0; j < 4; j++) {
                int o = 4 * tx + j;
                th0[j] = *(const unsigned long long*)
                    &th_s[((k * (HH / 2) + c2a) * OO + o) * 2];
                th1[j] = *(const unsigned long long*)
                    &th_s[((k * (HH / 2) + c2b) * OO + o) * 2];
            }
#pragma unroll
            for (int r = 0; r < RPT; r++) {
                const ulonglong2 zv = *(const ulonglong2*)
                    &z_s[(k * NP + row0 + r) * HH + 4 * c4];
#pragma unroll
                for (int j = 0; j < 4; j++) {
                    fma2(accC[r][j], zv.x, th0[j]);
                    fma2(accC[r][j], zv.y, th1[j]);
                }
            }
        }
    }

    // ---- epilogue: relu(gcn) + residual, scatter to out[b][o][n][tau] ----
#pragma unroll
    for (int r = 0; r < RPT; r++) {
        int n = row0 + r;
        if (n < NV) {
            float x0 = xs[(0 * NV + n) * 4 + 1];
            float x1 = xs[(1 * NV + n) * 4 + 1];
            float x2 = xs[(2 * NV + n) * 4 + 1];
#pragma unroll
            for (int j = 0; j < 4; j++) {
                int o = 4 * tx + j;
                float lo, hi;
                unpack2(lo, hi, accC[r][j]);
                float v = fmaxf(lo + hi, 0.f)
                        + x0 * rw_s[o * 3 + 0] + x1 * rw_s[o * 3 + 1]
                        + x2 * rw_s[o * 3 + 2] + rb_s[o];
                out[(((size_t)b * OO + o) * NV + n) * TT + tau] = v;
            }
        }
    }
}

// ---------------------------------------------------------------------------
extern "C" void kernel_launch(void* const* d_in, const int* in_sizes, int n_in,
                              void* d_out, int out_size)
{
    const float* x      = (const float*)d_in[0];
    const float* cheb   = (const float*)d_in[2];
    const float* conv_w = (const float*)d_in[3];
    const float* conv_b = (const float*)d_in[4];
    const float* theta  = (const float*)d_in[5];
    const float* res_w  = (const float*)d_in[6];
    const float* res_b  = (const float*)d_in[7];
    float* out = (float*)d_out;

    cudaFuncSetAttribute(fused_kernel,
                         cudaFuncAttributeMaxDynamicSharedMemorySize, SMEM_BYTES);

    cheb_transpose_kernel<<<KK, 256>>>(cheb);
    fused_kernel<<<dim3(TT, BB), NTHR, SMEM_BYTES>>>(
        x, conv_w, conv_b, theta, res_w, res_b, out);
}

// round 7
// speedup vs baseline: 1.9647x; 1.6851x over previous
#include <cuda_runtime.h>
#include <cstdint>

// Problem constants
#define BB 16
#define FIN 3
#define NV 170
#define TT 288
#define HH 64
#define OO 64
#define KK 3

#define NTHR 384
#define NWARP 12
#define NPAD 192           // padded n and m
#define TS_STRIDE 72       // t row stride (banks: 8*tig+g distinct)
#define CH_STRIDE 36       // cheb chunk row stride (banks: 4*g+tig distinct)
#define ZS_STRIDE 68       // z strip row stride
#define TH_STRIDE 72       // theta row stride

// smem offsets (floats)
#define XS_OFF 0                                  // [FIN][NV][4]
#define CW_OFF 2048
#define CB_OFF (CW_OFF + 576)                     // 2624
#define RW_OFF (CB_OFF + 64)                      // 2688
#define RB_OFF (RW_OFF + 192)                     // 2880
#define TS_OFF 2944                               // t tf32 [192][72]
#define TH_OFF (TS_OFF + NPAD * TS_STRIDE)        // 16768  theta tf32 [192][72]
#define CHUNK_OFF (TH_OFF + NPAD * TH_STRIDE)     // 30592  cheb chunk [192][36]
#define ZS_OFF (CHUNK_OFF + NPAD * CH_STRIDE)     // 37504  z strips [12][16][68]
#define SMEM_FLOATS (ZS_OFF + NWARP * 16 * ZS_STRIDE)  // 50560
#define SMEM_BYTES (SMEM_FLOATS * 4)              // 202240

// cheb pre-converted to tf32, zero-padded [K][192][192]
__device__ uint32_t g_chebP[KK * NPAD * NPAD];

__device__ __forceinline__ uint32_t f2tf32(float f) {
    uint32_t r; asm("cvt.rna.tf32.f32 %0, %1;" : "=r"(r) : "f"(f)); return r;
}

// m16n8k8 row.col tf32 MMA, fp32 accumulate (sm_80+, valid on sm_100)
__device__ __forceinline__ void mma8(float* c, const uint32_t* a,
                                     uint32_t b0, uint32_t b1) {
    asm volatile(
        "mma.sync.aligned.m16n8k8.row.col.f32.tf32.tf32.f32 "
        "{%0,%1,%2,%3}, {%4,%5,%6,%7}, {%8,%9}, {%0,%1,%2,%3};"
        : "+f"(c[0]), "+f"(c[1]), "+f"(c[2]), "+f"(c[3])
        : "r"(a[0]), "r"(a[1]), "r"(a[2]), "r"(a[3]), "r"(b0), "r"(b1));
}

// ---------------------------------------------------------------------------
// Kernel 1: cheb -> tf32, zero-padded to [K][192][192]
// ---------------------------------------------------------------------------
__global__ void prep_cheb_kernel(const float* __restrict__ cheb) {
    int k = blockIdx.x;
    for (int i = threadIdx.x; i < NPAD * NPAD; i += blockDim.x) {
        int n = i / NPAD, m = i % NPAD;
        float v = (n < NV && m < NV) ? cheb[(k * NV + n) * NV + m] : 0.f;
        g_chebP[k * NPAD * NPAD + i] = f2tf32(v);
    }
}

// ---------------------------------------------------------------------------
// Kernel 2: fused conv + ChebConv(mma) + theta(mma) + relu + residual.
// One block per (b,tau), 384 threads = 12 warps, warp w owns n rows [16w,16w+16)
// ---------------------------------------------------------------------------
__global__ __launch_bounds__(NTHR, 1) void fused_kernel(
    const float* __restrict__ x, const float* __restrict__ conv_w,
    const float* __restrict__ conv_b, const float* __restrict__ theta,
    const float* __restrict__ res_w, const float* __restrict__ res_b,
    float* __restrict__ out)
{
    extern __shared__ float smem[];
    float* xs   = smem + XS_OFF;
    float* cw_s = smem + CW_OFF;
    float* cb_s = smem + CB_OFF;
    float* rw_s = smem + RW_OFF;
    float* rb_s = smem + RB_OFF;
    uint32_t* ts_w  = (uint32_t*)(smem + TS_OFF);
    uint32_t* th_w  = (uint32_t*)(smem + TH_OFF);
    uint32_t* chk_w = (uint32_t*)(smem + CHUNK_OFF);

    const int tid = threadIdx.x;
    const int w = tid >> 5, lane = tid & 31;
    const int g = lane >> 2, tig = lane & 3;
    const int tau = blockIdx.x, b = blockIdx.y;

    uint32_t* zs = (uint32_t*)(smem + ZS_OFF) + w * 16 * ZS_STRIDE;

    // ---- phase 0: stage inputs ----
    for (int i = tid; i < FIN * NV; i += NTHR) {
        int f = i / NV, m = i % NV;
        const float* xr = x + (((size_t)b * FIN + f) * NV + m) * TT + tau;
        float* d = &xs[(f * NV + m) * 4];
        d[0] = (tau > 0)      ? xr[-1] : 0.f;
        d[1] = xr[0];
        d[2] = (tau < TT - 1) ? xr[1]  : 0.f;
    }
    for (int i = tid; i < HH * 9; i += NTHR) cw_s[i] = conv_w[i];
    if (tid < HH) cb_s[tid] = conv_b[tid];
    for (int i = tid; i < OO * FIN; i += NTHR) rw_s[i] = res_w[i];
    if (tid < OO) rb_s[tid] = res_b[tid];
    // theta tf32: th[(k*64+c)*72 + o]
    for (int i = tid; i < KK * HH * OO; i += NTHR) {
        int k = i / (HH * OO), c = (i / OO) % HH, o = i % OO;
        th_w[(k * HH + c) * TH_STRIDE + o] = f2tf32(theta[i]);
    }
    // zero t (covers pad rows 170-191)
    for (int i = tid; i < NPAD * TS_STRIDE; i += NTHR) ts_w[i] = 0u;
    __syncthreads();

    // ---- phase 1: temporal conv + ReLU -> t tf32 [m][c] stride 72 ----
    {
        int c = tid & 63, ml = tid >> 6;   // 6 m-lanes
        float wr[9];
#pragma unroll
        for (int i = 0; i < 9; i++) wr[i] = cw_s[c * 9 + i];
        float bv = cb_s[c];
        for (int m = ml; m < NV; m += 6) {
            float acc = bv;
#pragma unroll
            for (int f = 0; f < FIN; f++) {
                const float* xm = &xs[(f * NV + m) * 4];
                acc += xm[0] * wr[f * 3 + 0];
                acc += xm[1] * wr[f * 3 + 1];
                acc += xm[2] * wr[f * 3 + 2];
            }
            ts_w[m * TS_STRIDE + c] = f2tf32(fmaxf(acc, 0.f));
        }
    }

    // ---- stages B + C, fused per k ----
    float gcn[8][4];
#pragma unroll
    for (int ot = 0; ot < 8; ot++)
#pragma unroll
        for (int j = 0; j < 4; j++) gcn[ot][j] = 0.f;

    const int r0 = w * 16 + g;         // A-frag rows (and +8)

    for (int k = 0; k < KK; k++) {
        float accB[8][4];
#pragma unroll
        for (int ct = 0; ct < 8; ct++)
#pragma unroll
            for (int j = 0; j < 4; j++) accB[ct][j] = 0.f;

        // z[n][c] = sum_m cheb_k[n][m] * t[m][c] ; m streamed in chunks of 32
        for (int ch = 0; ch < 6; ch++) {
            __syncthreads();
            const uint32_t* src = g_chebP + (size_t)k * NPAD * NPAD + ch * 32;
            for (int i = tid; i < NPAD * 32; i += NTHR) {
                int n = i >> 5, ml = i & 31;
                chk_w[n * CH_STRIDE + ml] = src[n * NPAD + ml];
            }
            __syncthreads();

#pragma unroll
            for (int kk = 0; kk < 4; kk++) {
                int mb = kk * 8;
                uint32_t a[4];
                a[0] = chk_w[(r0)     * CH_STRIDE + mb + tig];
                a[1] = chk_w[(r0 + 8) * CH_STRIDE + mb + tig];
                a[2] = chk_w[(r0)     * CH_STRIDE + mb + tig + 4];
                a[3] = chk_w[(r0 + 8) * CH_STRIDE + mb + tig + 4];
                int gm = ch * 32 + mb;
                uint32_t b0[8], b1[8];
#pragma unroll
                for (int ct = 0; ct < 8; ct++) {
                    b0[ct] = ts_w[(gm + tig)     * TS_STRIDE + ct * 8 + g];
                    b1[ct] = ts_w[(gm + tig + 4) * TS_STRIDE + ct * 8 + g];
                }
#pragma unroll
                for (int ct = 0; ct < 8; ct++)
                    mma8(accB[ct], a, b0[ct], b1[ct]);
            }
        }

        // spill z strip (tf32) to this warp's private smem
#pragma unroll
        for (int ct = 0; ct < 8; ct++) {
            zs[(g)     * ZS_STRIDE + ct * 8 + 2 * tig]     = f2tf32(accB[ct][0]);
            zs[(g)     * ZS_STRIDE + ct * 8 + 2 * tig + 1] = f2tf32(accB[ct][1]);
            zs[(g + 8) * ZS_STRIDE + ct * 8 + 2 * tig]     = f2tf32(accB[ct][2]);
            zs[(g + 8) * ZS_STRIDE + ct * 8 + 2 * tig + 1] = f2tf32(accB[ct][3]);
        }
        __syncwarp();

        // gcn += z_strip @ theta_k
#pragma unroll
        for (int kk = 0; kk < 8; kk++) {
            uint32_t a[4];
            a[0] = zs[(g)     * ZS_STRIDE + kk * 8 + tig];
            a[1] = zs[(g + 8) * ZS_STRIDE + kk * 8 + tig];
            a[2] = zs[(g)     * ZS_STRIDE + kk * 8 + tig + 4];
            a[3] = zs[(g + 8) * ZS_STRIDE + kk * 8 + tig + 4];
            int rb = k * HH + kk * 8;
#pragma unroll
            for (int ot = 0; ot < 8; ot++) {
                uint32_t b0 = th_w[(rb + tig)     * TH_STRIDE + ot * 8 + g];
                uint32_t b1 = th_w[(rb + tig + 4) * TH_STRIDE + ot * 8 + g];
                mma8(gcn[ot], a, b0, b1);
            }
        }
        __syncwarp();
    }

    // ---- epilogue: relu(gcn) + residual, scatter to out[b][o][n][tau] ----
    {
        int n0 = r0, n1 = r0 + 8;
        float x0a = 0.f, x1a = 0.f, x2a = 0.f, x0b = 0.f, x1b = 0.f, x2b = 0.f;
        if (n0 < NV) {
            x0a = xs[(0 * NV + n0) * 4 + 1];
            x1a = xs[(1 * NV + n0) * 4 + 1];
            x2a = xs[(2 * NV + n0) * 4 + 1];
        }
        if (n1 < NV) {
            x0b = xs[(0 * NV + n1) * 4 + 1];
            x1b = xs[(1 * NV + n1) * 4 + 1];
            x2b = xs[(2 * NV + n1) * 4 + 1];
        }
        float* ob = out + ((size_t)b * OO) * NV * TT + tau;
#pragma unroll
        for (int ot = 0; ot < 8; ot++) {
#pragma unroll
            for (int j = 0; j < 2; j++) {
                int o = ot * 8 + 2 * tig + j;
                float rw0 = rw_s[o * 3 + 0], rw1 = rw_s[o * 3 + 1],
                      rw2 = rw_s[o * 3 + 2], rbv = rb_s[o];
                if (n0 < NV)
                    ob[((size_t)o * NV + n0) * TT] =
                        fmaxf(gcn[ot][j], 0.f) + x0a * rw0 + x1a * rw1 + x2a * rw2 + rbv;
                if (n1 < NV)
                    ob[((size_t)o * NV + n1) * TT] =
                        fmaxf(gcn[ot][2 + j], 0.f) + x0b * rw0 + x1b * rw1 + x2b * rw2 + rbv;
            }
        }
    }
}

// ---------------------------------------------------------------------------
extern "C" void kernel_launch(void* const* d_in, const int* in_sizes, int n_in,
                              void* d_out, int out_size)
{
    const float* x      = (const float*)d_in[0];
    const float* cheb   = (const float*)d_in[2];
    const float* conv_w = (const float*)d_in[3];
    const float* conv_b = (const float*)d_in[4];
    const float* theta  = (const float*)d_in[5];
    const float* res_w  = (const float*)d_in[6];
    const float* res_b  = (const float*)d_in[7];
    float* out = (float*)d_out;

    cudaFuncSetAttribute(fused_kernel,
                         cudaFuncAttributeMaxDynamicSharedMemorySize, SMEM_BYTES);

    prep_cheb_kernel<<<KK, 256>>>(cheb);
    fused_kernel<<<dim3(TT, BB), NTHR, SMEM_BYTES>>>(
        x, conv_w, conv_b, theta, res_w, res_b, out);
}

// round 10
// speedup vs baseline: 3.8629x; 1.9662x over previous
#include <cuda_runtime.h>
#include <cuda_fp16.h>
#include <cstdint>

// Problem constants
#define BB 16
#define FIN 3
#define NV 170
#define TT 288
#define HH 64
#define OO 64
#define KK 3

#define NTHR 384
#define NWARP 12
#define NPAD 192

// half-array strides (in halves): multiple of 8 (16B rows) and /8 odd -> conflict-free
#define TS_STRIDE 72
#define TH_STRIDE 72
#define ZS_STRIDE 72
#define CK_STRIDE 40        // chunk row: 32 data + 8 pad halves (80B = 5*16B)

// float-region offsets (floats)
#define XS_OFF 0
#define CW_OFF 2048
#define CB_OFF (CW_OFF + 576)
#define RW_OFF (CB_OFF + 64)
#define RB_OFF (RW_OFF + 192)
// byte offsets for half regions
#define TS_B   11776                          // t fp16 [192][72]
#define TH_B   (TS_B + NPAD * TS_STRIDE * 2)  // 39424 theta fp16 [192][72]
#define CK_B   (TH_B + NPAD * TH_STRIDE * 2)  // 67072 two chunk bufs [192][40]
#define CK_BYTES (NPAD * CK_STRIDE * 2)       // 15360
#define ZS_B   (CK_B + 2 * CK_BYTES)          // 97792 z strips [12][16][72]
#define SMEM_BYTES (ZS_B + NWARP * 16 * ZS_STRIDE * 2)   // 125440

// cheb fp16, zero-padded [K][192][192]
__device__ __half g_chebH[KK * NPAD * NPAD];

__device__ __forceinline__ uint32_t smem_u32(const void* p) {
    uint32_t a;
    asm("{ .reg .u64 t; cvta.to.shared.u64 t, %1; cvt.u32.u64 %0, t; }"
        : "=r"(a) : "l"(p));
    return a;
}
__device__ __forceinline__ uint32_t pack_h2(float a, float b) {
    __half2 h = __floats2half2_rn(a, b);          // memory: [a][b]
    return *reinterpret_cast<uint32_t*>(&h);      // full 32 bits
}
__device__ __forceinline__ void mma16(float* c, const uint32_t* a,
                                      uint32_t b0, uint32_t b1) {
    asm volatile(
        "mma.sync.aligned.m16n8k16.row.col.f32.f16.f16.f32 "
        "{%0,%1,%2,%3}, {%4,%5,%6,%7}, {%8,%9}, {%0,%1,%2,%3};"
        : "+f"(c[0]), "+f"(c[1]), "+f"(c[2]), "+f"(c[3])
        : "r"(a[0]), "r"(a[1]), "r"(a[2]), "r"(a[3]), "r"(b0), "r"(b1));
}
#define LDSM4(r, addr) \
    asm volatile("ldmatrix.sync.aligned.m8n8.x4.shared.b16 {%0,%1,%2,%3}, [%4];" \
        : "=r"((r)[0]), "=r"((r)[1]), "=r"((r)[2]), "=r"((r)[3]) : "r"(addr))
#define LDSM4T(r, addr) \
    asm volatile("ldmatrix.sync.aligned.m8n8.x4.trans.shared.b16 {%0,%1,%2,%3}, [%4];" \
        : "=r"((r)[0]), "=r"((r)[1]), "=r"((r)[2]), "=r"((r)[3]) : "r"(addr))
#define STS32(addr, val) \
    asm volatile("st.shared.u32 [%0], %1;" :: "r"(addr), "r"(val) : "memory")
#define CP16(dst, src) \
    asm volatile("cp.async.cg.shared.global [%0], [%1], 16;" :: "r"(dst), "l"(src))
#define CP_COMMIT() asm volatile("cp.async.commit_group;" ::: "memory")
#define CP_WAIT0()  asm volatile("cp.async.wait_group 0;" ::: "memory")

// ---------------------------------------------------------------------------
// Kernel 1: cheb -> fp16, zero-padded [K][192][192]
// ---------------------------------------------------------------------------
__global__ void prep_cheb_kernel(const float* __restrict__ cheb) {
    int k = blockIdx.x;
    for (int i = threadIdx.x; i < NPAD * NPAD; i += blockDim.x) {
        int n = i / NPAD, m = i % NPAD;
        float v = (n < NV && m < NV) ? cheb[(k * NV + n) * NV + m] : 0.f;
        g_chebH[k * NPAD * NPAD + i] = __float2half_rn(v);
    }
}

// async-load 32-m-column chunk gc into chunk buffer (768 x 16B ops)
__device__ __forceinline__ void load_chunk_async(uint32_t dst_base, int gc, int tid) {
    const __half* src = g_chebH + (size_t)(gc / 6) * NPAD * NPAD + (gc % 6) * 32;
#pragma unroll
    for (int j = 0; j < 2; j++) {
        int e = tid + j * NTHR;                 // 0..767
        int row = e >> 2, q = e & 3;
        uint32_t dst = dst_base + row * (CK_STRIDE * 2) + q * 16;
        CP16(dst, src + row * NPAD + q * 8);
    }
    CP_COMMIT();
}

// ---------------------------------------------------------------------------
// Kernel 2: fused conv + ChebConv(mma) + theta(mma) + relu + residual.
// One block per (b,tau), 384 threads = 12 warps; warp w owns n rows [16w,16w+16)
// ---------------------------------------------------------------------------
__global__ __launch_bounds__(NTHR, 1) void fused_kernel(
    const float* __restrict__ x, const float* __restrict__ conv_w,
    const float* __restrict__ conv_b, const float* __restrict__ theta,
    const float* __restrict__ res_w, const float* __restrict__ res_b,
    float* __restrict__ out)
{
    extern __shared__ float smem[];
    const uint32_t sb = smem_u32(smem);
    float* xs   = smem + XS_OFF;
    float* cw_s = smem + CW_OFF;
    float* cb_s = smem + CB_OFF;
    float* rw_s = smem + RW_OFF;
    float* rb_s = smem + RB_OFF;
    __half* ts_h = (__half*)((char*)smem + TS_B);
    __half* th_h = (__half*)((char*)smem + TH_B);

    const int tid = threadIdx.x;
    const int w = tid >> 5, lane = tid & 31;
    const int g = lane >> 2, tig = lane & 3;
    const int tau = blockIdx.x, b = blockIdx.y;

    // kick off chunk 0 prefetch immediately
    load_chunk_async(sb + CK_B, 0, tid);

    // ---- phase 0: stage inputs ----
    for (int i = tid; i < FIN * NV; i += NTHR) {
        int f = i / NV, m = i % NV;
        const float* xr = x + (((size_t)b * FIN + f) * NV + m) * TT + tau;
        float* d = &xs[(f * NV + m) * 4];
        d[0] = (tau > 0)      ? xr[-1] : 0.f;
        d[1] = xr[0];
        d[2] = (tau < TT - 1) ? xr[1]  : 0.f;
    }
    for (int i = tid; i < HH * 9; i += NTHR) cw_s[i] = conv_w[i];
    if (tid < HH) cb_s[tid] = conv_b[tid];
    for (int i = tid; i < OO * FIN; i += NTHR) rw_s[i] = res_w[i];
    if (tid < OO) rb_s[tid] = res_b[tid];
    for (int i = tid; i < KK * HH * OO; i += NTHR) {
        int k = i / (HH * OO), c = (i / OO) % HH, o = i % OO;
        th_h[(k * HH + c) * TH_STRIDE + o] = __float2half_rn(theta[i]);
    }
    // zero t pad rows 170..191
    {
        uint32_t* tz = (uint32_t*)(ts_h + NV * TS_STRIDE);
        for (int i = tid; i < ((NPAD - NV) * TS_STRIDE) / 2; i += NTHR) tz[i] = 0u;
    }
    __syncthreads();  // xs/cw ready for phase 1

    // ---- phase 1: temporal conv + ReLU -> t fp16 [m][c] ----
    {
        int c = tid & 63, ml = tid >> 6;   // 6 m-lanes
        float wr[9];
#pragma unroll
        for (int i = 0; i < 9; i++) wr[i] = cw_s[c * 9 + i];
        float bv = cb_s[c];
        for (int m = ml; m < NV; m += 6) {
            float acc = bv;
#pragma unroll
            for (int f = 0; f < FIN; f++) {
                const float* xm = &xs[(f * NV + m) * 4];
                acc += xm[0] * wr[f * 3 + 0];
                acc += xm[1] * wr[f * 3 + 1];
                acc += xm[2] * wr[f * 3 + 2];
            }
            ts_h[m * TS_STRIDE + c] = __float2half_rn(fmaxf(acc, 0.f));
        }
    }

    // per-lane ldmatrix address components
    const int arow = 16 * w + (lane & 15);                    // A rows (chunk/z local)
    const int acol16 = (lane >> 4) * 16;                      // A col byte offset
    const int trow = (lane & 7) + ((lane >> 3) & 1) * 8;      // B k-row within 16
    const int tcol16 = (lane >> 4) * 16;                      // B n col byte offset
    const uint32_t z_base = sb + ZS_B + w * (16 * ZS_STRIDE * 2);
    const uint32_t zA_addr = z_base + (lane & 15) * (ZS_STRIDE * 2) + acol16;

    float gcn[8][4];
#pragma unroll
    for (int ot = 0; ot < 8; ot++)
#pragma unroll
        for (int j = 0; j < 4; j++) gcn[ot][j] = 0.f;

    for (int k = 0; k < KK; k++) {
        float accB[8][4];
#pragma unroll
        for (int ct = 0; ct < 8; ct++)
#pragma unroll
            for (int j = 0; j < 4; j++) accB[ct][j] = 0.f;

        for (int ch = 0; ch < 6; ch++) {
            int gc = k * 6 + ch;
            CP_WAIT0();
            __syncthreads();              // buf[gc&1] ready; prior compute done
            if (gc < KK * 6 - 1)
                load_chunk_async(sb + CK_B + ((gc + 1) & 1) * CK_BYTES, gc + 1, tid);

            uint32_t ck_addr = sb + CK_B + (gc & 1) * CK_BYTES
                             + arow * (CK_STRIDE * 2) + acol16;
#pragma unroll
            for (int kk = 0; kk < 2; kk++) {
                uint32_t a[4];
                LDSM4(a, ck_addr + kk * 32);
                uint32_t bb[8][2];
                uint32_t tb = sb + TS_B
                            + (ch * 32 + kk * 16 + trow) * (TS_STRIDE * 2) + tcol16;
#pragma unroll
                for (int p = 0; p < 4; p++) {
                    uint32_t t4[4];
                    LDSM4T(t4, tb + p * 32);
                    bb[2 * p][0] = t4[0]; bb[2 * p][1] = t4[1];
                    bb[2 * p + 1][0] = t4[2]; bb[2 * p + 1][1] = t4[3];
                }
#pragma unroll
                for (int ct = 0; ct < 8; ct++)
                    mma16(accB[ct], a, bb[ct][0], bb[ct][1]);
            }
        }

        // spill z strip to warp-private smem as fp16 (full 32-bit half2 packs)
#pragma unroll
        for (int ct = 0; ct < 8; ct++) {
            uint32_t lo = pack_h2(accB[ct][0], accB[ct][1]);
            uint32_t hi = pack_h2(accB[ct][2], accB[ct][3]);
            STS32(z_base + (g * ZS_STRIDE + ct * 8 + 2 * tig) * 2, lo);
            STS32(z_base + ((g + 8) * ZS_STRIDE + ct * 8 + 2 * tig) * 2, hi);
        }
        __syncwarp();

        // stage C: gcn += z_strip @ theta_k
#pragma unroll
        for (int kk = 0; kk < 4; kk++) {
            uint32_t a[4];
            LDSM4(a, zA_addr + kk * 32);
            uint32_t bo[8][2];
            uint32_t hb = sb + TH_B
                        + (k * HH + kk * 16 + trow) * (TH_STRIDE * 2) + tcol16;
#pragma unroll
            for (int p = 0; p < 4; p++) {
                uint32_t t4[4];
                LDSM4T(t4, hb + p * 32);
                bo[2 * p][0] = t4[0]; bo[2 * p][1] = t4[1];
                bo[2 * p + 1][0] = t4[2]; bo[2 * p + 1][1] = t4[3];
            }
#pragma unroll
            for (int ot = 0; ot < 8; ot++)
                mma16(gcn[ot], a, bo[ot][0], bo[ot][1]);
        }
        __syncwarp();
    }

    // ---- epilogue: relu(gcn) + residual, scatter to out[b][o][n][tau] ----
    {
        int n0 = 16 * w + g, n1 = n0 + 8;
        float x0a = 0.f, x1a = 0.f, x2a = 0.f, x0b = 0.f, x1b = 0.f, x2b = 0.f;
        if (n0 < NV) {
            x0a = xs[(0 * NV + n0) * 4 + 1];
            x1a = xs[(1 * NV + n0) * 4 + 1];
            x2a = xs[(2 * NV + n0) * 4 + 1];
        }
        if (n1 < NV) {
            x0b = xs[(0 * NV + n1) * 4 + 1];
            x1b = xs[(1 * NV + n1) * 4 + 1];
            x2b = xs[(2 * NV + n1) * 4 + 1];
        }
        float* ob = out + ((size_t)b * OO) * NV * TT + tau;
#pragma unroll
        for (int ot = 0; ot < 8; ot++) {
#pragma unroll
            for (int j = 0; j < 2; j++) {
                int o = ot * 8 + 2 * tig + j;
                float rw0 = rw_s[o * 3 + 0], rw1 = rw_s[o * 3 + 1],
                      rw2 = rw_s[o * 3 + 2], rbv = rb_s[o];
                if (n0 < NV)
                    ob[((size_t)o * NV + n0) * TT] =
                        fmaxf(gcn[ot][j], 0.f) + x0a * rw0 + x1a * rw1 + x2a * rw2 + rbv;
                if (n1 < NV)
                    ob[((size_t)o * NV + n1) * TT] =
                        fmaxf(gcn[ot][2 + j], 0.f) + x0b * rw0 + x1b * rw1 + x2b * rw2 + rbv;
            }
        }
    }
}

// ---------------------------------------------------------------------------
extern "C" void kernel_launch(void* const* d_in, const int* in_sizes, int n_in,
                              void* d_out, int out_size)
{
    const float* x      = (const float*)d_in[0];
    const float* cheb   = (const float*)d_in[2];
    const float* conv_w = (const float*)d_in[3];
    const float* conv_b = (const float*)d_in[4];
    const float* theta  = (const float*)d_in[5];
    const float* res_w  = (const float*)d_in[6];
    const float* res_b  = (const float*)d_in[7];
    float* out = (float*)d_out;

    cudaFuncSetAttribute(fused_kernel,
                         cudaFuncAttributeMaxDynamicSharedMemorySize, SMEM_BYTES);

    prep_cheb_kernel<<<KK, 256>>>(cheb);
    fused_kernel<<<dim3(TT, BB), NTHR, SMEM_BYTES>>>(
        x, conv_w, conv_b, theta, res_w, res_b, out);
}